// round 13
// baseline (speedup 1.0000x reference)
#include <cuda_runtime.h>
#include <cuda_bf16.h>
#include <math.h>
#include <float.h>
#include <cstdint>

// ============================================================================
// Fused attention block via mma.sync bf16 (base PTX features only — the
// harness compiles at compute_103, which rejects all tcgen05/"a" features).
// Split-bf16 x3 precision scheme. Shapes fixed:
// x[4,2048,1024], w_qkv[1536,1024], w_out[1024,512], b_out[1024] -> out fp32.
// ============================================================================

#define NTHREADS 256

// ---------------- scratch (device globals; allocation-free) ----------------
__device__ float        g_qkv[8192 * 1536];
__device__ float        g_S  [4LL * 2048 * 2048];
__device__ float        g_att[8192 * 512];
__device__ __nv_bfloat16 g_x_hi [8192 * 1024];
__device__ __nv_bfloat16 g_x_lo [8192 * 1024];
__device__ __nv_bfloat16 g_wqkv_hi[1536 * 1024];
__device__ __nv_bfloat16 g_wqkv_lo[1536 * 1024];
__device__ __nv_bfloat16 g_wout_hi[1024 * 512];
__device__ __nv_bfloat16 g_wout_lo[1024 * 512];
__device__ __nv_bfloat16 g_q_hi[8192 * 512];
__device__ __nv_bfloat16 g_q_lo[8192 * 512];
__device__ __nv_bfloat16 g_k_hi[8192 * 512];
__device__ __nv_bfloat16 g_k_lo[8192 * 512];
__device__ __nv_bfloat16 g_vt_hi[4LL * 512 * 2048];   // transposed V [b][d][j]
__device__ __nv_bfloat16 g_vt_lo[4LL * 512 * 2048];
__device__ __nv_bfloat16 g_p_hi[4LL * 2048 * 2048];
__device__ __nv_bfloat16 g_p_lo[4LL * 2048 * 2048];
__device__ __nv_bfloat16 g_att_hi[8192 * 512];
__device__ __nv_bfloat16 g_att_lo[8192 * 512];

// ---------------- helpers ----------------
__device__ __forceinline__ uint32_t smem_u32(const void* p) {
    uint32_t a;
    asm("{ .reg .u64 t; cvta.to.shared.u64 t, %1; cvt.u32.u64 %0, t; }"
        : "=r"(a) : "l"(p));
    return a;
}
__device__ __forceinline__ void ldsm_x4(uint32_t* f, uint32_t addr) {
    asm volatile("ldmatrix.sync.aligned.m8n8.x4.shared.b16 {%0,%1,%2,%3}, [%4];"
                 : "=r"(f[0]), "=r"(f[1]), "=r"(f[2]), "=r"(f[3]) : "r"(addr));
}
__device__ __forceinline__ void mma16816(float* d, const uint32_t* a,
                                         uint32_t b0, uint32_t b1) {
    asm volatile("mma.sync.aligned.m16n8k16.row.col.f32.bf16.bf16.f32 "
                 "{%0,%1,%2,%3}, {%4,%5,%6,%7}, {%8,%9}, {%0,%1,%2,%3};"
                 : "+f"(d[0]), "+f"(d[1]), "+f"(d[2]), "+f"(d[3])
                 : "r"(a[0]), "r"(a[1]), "r"(a[2]), "r"(a[3]), "r"(b0), "r"(b1));
}

// ---------------------------------------------------------------------------
// mma.sync split-bf16 GEMM.  C[m,n] = alpha * sum_k A[m,k]*B[n,k]  (+bias[n])
// A = Ahi+Alo, B = Bhi+Blo. 3-term product (drops lo*lo).
// CMODE 0: dense  1: causal tile-skip  2: K clamped to (rowtile+1)*128.
// M,N multiples of 128; K multiple of 32. Batched via blockIdx.z strides.
// CTA tile 128x128, 8 warps in 4(M) x 2(N), warp tile 32x64.
// ---------------------------------------------------------------------------
#define KB 32                        // K elements per stage
#define ROWB 80                      // padded smem row stride (bytes): 64B data
#define TILE_B (128 * ROWB)          // 10240 B per operand tile
#define STAGE_B (4 * TILE_B)         // Ahi, Alo, Bhi, Blo
#define DYN_SMEM (2 * STAGE_B)       // 81920 B double-buffered

template <int CMODE>
__global__ void __launch_bounds__(NTHREADS, 1)
gemm_bf16x3(const __nv_bfloat16* __restrict__ Ahi, const __nv_bfloat16* __restrict__ Alo,
            const __nv_bfloat16* __restrict__ Bhi, const __nv_bfloat16* __restrict__ Blo,
            float* __restrict__ C, const float* __restrict__ bias,
            int K, int lda, int ldb, int ldc,
            long long sA, long long sB, long long sC, float alpha)
{
    if (CMODE == 1 && blockIdx.x > blockIdx.y) return;

    extern __shared__ char smem[];
    const uint32_t sbase = smem_u32(smem);

    const int t    = threadIdx.x;
    const int lane = t & 31;
    const int wid  = t >> 5;
    const int wm   = wid & 3;    // 0..3 : M position (32 rows each)
    const int wn   = wid >> 2;   // 0..1 : N position (64 cols each)

    const long long bz = blockIdx.z;
    Ahi += bz * sA;  Alo += bz * sA;
    Bhi += bz * sB;  Blo += bz * sB;
    C   += bz * sC;

    const int row0 = blockIdx.y * 128;
    const int col0 = blockIdx.x * 128;

    int Keff = K;
    if (CMODE == 2) {
        int lim = (int)(blockIdx.y + 1) * 128;
        Keff = (lim < K) ? lim : K;
    }
    const int nstages = Keff / KB;

    float acc[2][8][4];
#pragma unroll
    for (int i = 0; i < 2; i++)
#pragma unroll
        for (int j = 0; j < 8; j++)
#pragma unroll
            for (int r = 0; r < 4; r++) acc[i][j][r] = 0.0f;

    // loader geometry: per operand 512 chunks of 16B; thread t -> chunks t, t+256
    const int ldrow0 = (t)        >> 2, ldcc0 = (t)        & 3;
    const int ldrow1 = (t + 256)  >> 2, ldcc1 = (t + 256)  & 3;

    int4 stg[4][2];

    // ---- prologue: load + store stage 0 ----
    {
        const int k0 = 0;
        const __nv_bfloat16* s0 = Ahi + (long long)(row0 + ldrow0) * lda + k0 + ldcc0 * 8;
        const __nv_bfloat16* s1 = Ahi + (long long)(row0 + ldrow1) * lda + k0 + ldcc1 * 8;
        stg[0][0] = *(const int4*)s0;  stg[0][1] = *(const int4*)s1;
        s0 = Alo + (long long)(row0 + ldrow0) * lda + k0 + ldcc0 * 8;
        s1 = Alo + (long long)(row0 + ldrow1) * lda + k0 + ldcc1 * 8;
        stg[1][0] = *(const int4*)s0;  stg[1][1] = *(const int4*)s1;
        s0 = Bhi + (long long)(col0 + ldrow0) * ldb + k0 + ldcc0 * 8;
        s1 = Bhi + (long long)(col0 + ldrow1) * ldb + k0 + ldcc1 * 8;
        stg[2][0] = *(const int4*)s0;  stg[2][1] = *(const int4*)s1;
        s0 = Blo + (long long)(col0 + ldrow0) * ldb + k0 + ldcc0 * 8;
        s1 = Blo + (long long)(col0 + ldrow1) * ldb + k0 + ldcc1 * 8;
        stg[3][0] = *(const int4*)s0;  stg[3][1] = *(const int4*)s1;
#pragma unroll
        for (int op = 0; op < 4; op++) {
            *(int4*)(smem + op * TILE_B + ldrow0 * ROWB + ldcc0 * 16) = stg[op][0];
            *(int4*)(smem + op * TILE_B + ldrow1 * ROWB + ldcc1 * 16) = stg[op][1];
        }
    }
    __syncthreads();

    for (int s = 0; s < nstages; ++s) {
        const int b = s & 1;

        // prefetch next stage into registers
        if (s + 1 < nstages) {
            const int k0 = (s + 1) * KB;
            const __nv_bfloat16* s0 = Ahi + (long long)(row0 + ldrow0) * lda + k0 + ldcc0 * 8;
            const __nv_bfloat16* s1 = Ahi + (long long)(row0 + ldrow1) * lda + k0 + ldcc1 * 8;
            stg[0][0] = *(const int4*)s0;  stg[0][1] = *(const int4*)s1;
            s0 = Alo + (long long)(row0 + ldrow0) * lda + k0 + ldcc0 * 8;
            s1 = Alo + (long long)(row0 + ldrow1) * lda + k0 + ldcc1 * 8;
            stg[1][0] = *(const int4*)s0;  stg[1][1] = *(const int4*)s1;
            s0 = Bhi + (long long)(col0 + ldrow0) * ldb + k0 + ldcc0 * 8;
            s1 = Bhi + (long long)(col0 + ldrow1) * ldb + k0 + ldcc1 * 8;
            stg[2][0] = *(const int4*)s0;  stg[2][1] = *(const int4*)s1;
            s0 = Blo + (long long)(col0 + ldrow0) * ldb + k0 + ldcc0 * 8;
            s1 = Blo + (long long)(col0 + ldrow1) * ldb + k0 + ldcc1 * 8;
            stg[3][0] = *(const int4*)s0;  stg[3][1] = *(const int4*)s1;
        }

        // ---- compute on buffer b ----
        const uint32_t sA0 = sbase + b * STAGE_B;             // Ahi
        const uint32_t sB0 = sA0 + 2 * TILE_B;                // Bhi
#pragma unroll
        for (int ks = 0; ks < 2; ++ks) {
            uint32_t ah[2][4], al[2][4];
#pragma unroll
            for (int i = 0; i < 2; i++) {
                const uint32_t r  = wm * 32 + i * 16 + (lane & 15);
                const uint32_t cb = ks * 32 + ((lane >> 4) << 4);
                const uint32_t ad = sA0 + r * ROWB + cb;
                ldsm_x4(ah[i], ad);
                ldsm_x4(al[i], ad + TILE_B);
            }
            uint32_t bh[4][4], bl[4][4];
#pragma unroll
            for (int jj = 0; jj < 4; jj++) {
                const uint32_t r  = wn * 64 + jj * 16 + (lane & 7) + ((lane >> 4) << 3);
                const uint32_t cb = (((lane >> 3) & 1) << 4) + ks * 32;
                const uint32_t ad = sB0 + r * ROWB + cb;
                ldsm_x4(bh[jj], ad);
                ldsm_x4(bl[jj], ad + TILE_B);
            }
#pragma unroll
            for (int i = 0; i < 2; i++)
#pragma unroll
                for (int j = 0; j < 8; j++) {
                    const int jj = j >> 1, o = (j & 1) * 2;
                    mma16816(acc[i][j], ah[i], bh[jj][o], bh[jj][o + 1]);
                    mma16816(acc[i][j], ah[i], bl[jj][o], bl[jj][o + 1]);
                    mma16816(acc[i][j], al[i], bh[jj][o], bh[jj][o + 1]);
                }
        }
        __syncthreads();

        // store prefetched stage into the other buffer
        if (s + 1 < nstages) {
            char* dst = smem + (b ^ 1) * STAGE_B;
#pragma unroll
            for (int op = 0; op < 4; op++) {
                *(int4*)(dst + op * TILE_B + ldrow0 * ROWB + ldcc0 * 16) = stg[op][0];
                *(int4*)(dst + op * TILE_B + ldrow1 * ROWB + ldcc1 * 16) = stg[op][1];
            }
            __syncthreads();
        }
    }

    // ---- epilogue ----
    const int rbase = row0 + wm * 32;
    const int cbase = col0 + wn * 64;
    const int lr = lane >> 2;
    const int lc = (lane & 3) * 2;
#pragma unroll
    for (int i = 0; i < 2; i++)
#pragma unroll
        for (int j = 0; j < 8; j++) {
            const int col = cbase + j * 8 + lc;
            const float b0 = bias ? bias[col]     : 0.0f;
            const float b1 = bias ? bias[col + 1] : 0.0f;
            const int r1 = rbase + i * 16 + lr;
            float2 v0 = { acc[i][j][0] * alpha + b0, acc[i][j][1] * alpha + b1 };
            float2 v1 = { acc[i][j][2] * alpha + b0, acc[i][j][3] * alpha + b1 };
            *(float2*)(C + (long long)r1 * ldc + col)       = v0;
            *(float2*)(C + (long long)(r1 + 8) * ldc + col) = v1;
        }
}

// ---------------------------------------------------------------------------
// Conversion kernels
// ---------------------------------------------------------------------------
__device__ __forceinline__ void split1(float v, __nv_bfloat16* h, __nv_bfloat16* l) {
    __nv_bfloat16 hh = __float2bfloat16(v);
    *h = hh;
    *l = __float2bfloat16(v - __bfloat162float(hh));
}

__global__ void __launch_bounds__(NTHREADS)
split_f32(const float* __restrict__ src, __nv_bfloat16* __restrict__ hi,
          __nv_bfloat16* __restrict__ lo, long long n)
{
    long long stride = (long long)gridDim.x * NTHREADS;
    for (long long i = (long long)blockIdx.x * NTHREADS + threadIdx.x; i < n; i += stride) {
        split1(src[i], hi + i, lo + i);
    }
}

__global__ void __launch_bounds__(NTHREADS)
split_qk(const float* __restrict__ qkv,
         __nv_bfloat16* __restrict__ qh, __nv_bfloat16* __restrict__ ql,
         __nv_bfloat16* __restrict__ kh, __nv_bfloat16* __restrict__ kl)
{
    const long long n = 8192LL * 512;
    long long stride = (long long)gridDim.x * NTHREADS;
    for (long long i = (long long)blockIdx.x * NTHREADS + threadIdx.x; i < n; i += stride) {
        long long m = i >> 9;
        int c = (int)(i & 511);
        const float* row = qkv + m * 1536;
        split1(row[c],       qh + i, ql + i);
        split1(row[512 + c], kh + i, kl + i);
    }
}

__global__ void __launch_bounds__(256)
split_v_t(const float* __restrict__ qkv,
          __nv_bfloat16* __restrict__ vh, __nv_bfloat16* __restrict__ vl)
{
    __shared__ float tile[32][33];
    const int b  = blockIdx.z;
    const int j0 = blockIdx.x * 32;
    const int d0 = blockIdx.y * 32;
    const int tx = threadIdx.x;
    const int ty = threadIdx.y;
#pragma unroll
    for (int r = 0; r < 32; r += 8) {
        int jj = ty + r;
        tile[jj][tx] = qkv[((long long)(b * 2048 + j0 + jj)) * 1536 + 1024 + d0 + tx];
    }
    __syncthreads();
#pragma unroll
    for (int r = 0; r < 32; r += 8) {
        int dd = ty + r;
        float v = tile[tx][dd];
        long long o = ((long long)(b * 512 + d0 + dd)) * 2048 + j0 + tx;
        split1(v, vh + o, vl + o);
    }
}

__global__ void __launch_bounds__(NTHREADS)
split_p(const float* __restrict__ S,
        __nv_bfloat16* __restrict__ ph, __nv_bfloat16* __restrict__ pl)
{
    const int i = blockIdx.x;
    const int b = blockIdx.y;
    const int padded = ((i + 128) >> 7) << 7;
    const long long o = ((long long)b * 2048 + i) * 2048;
    const float* row = S + o;
    for (int j = threadIdx.x; j < padded; j += NTHREADS) {
        split1(row[j], ph + o + j, pl + o + j);
    }
}

// ---------------------------------------------------------------------------
// Causal row softmax (in-place, zero-pads to row-tile boundary)
// ---------------------------------------------------------------------------
__global__ void __launch_bounds__(NTHREADS)
softmax_causal(float* __restrict__ S, int n)
{
    __shared__ float red[NTHREADS];
    const int i = blockIdx.x;
    const int b = blockIdx.y;
    const int t = threadIdx.x;
    float* row = S + ((long long)b * n + i) * n;
    const int valid = i + 1;

    float m = -FLT_MAX;
    for (int j = t; j < valid; j += NTHREADS) m = fmaxf(m, row[j]);
    red[t] = m;
    __syncthreads();
    for (int s = NTHREADS / 2; s > 0; s >>= 1) {
        if (t < s) red[t] = fmaxf(red[t], red[t + s]);
        __syncthreads();
    }
    m = red[0];
    __syncthreads();

    float sum = 0.0f;
    for (int j = t; j < valid; j += NTHREADS) {
        float e = __expf(row[j] - m);
        row[j] = e;
        sum += e;
    }
    red[t] = sum;
    __syncthreads();
    for (int s = NTHREADS / 2; s > 0; s >>= 1) {
        if (t < s) red[t] += red[t + s];
        __syncthreads();
    }
    const float inv = 1.0f / red[0];
    __syncthreads();

    for (int j = t; j < valid; j += NTHREADS) row[j] *= inv;

    const int padded = ((valid + 127) >> 7) << 7;
    for (int j = valid + t; j < padded; j += NTHREADS) row[j] = 0.0f;
}

// ---------------------------------------------------------------------------
extern "C" void kernel_launch(void* const* d_in, const int* in_sizes, int n_in,
                              void* d_out, int out_size)
{
    const float* x     = (const float*)d_in[0];
    const float* w_qkv = (const float*)d_in[1];
    const float* w_out = (const float*)d_in[2];
    const float* b_out = (const float*)d_in[3];
    float* out = (float*)d_out;

    float *qkv, *S, *att;
    __nv_bfloat16 *xh, *xl, *wqh, *wql, *woh, *wol;
    __nv_bfloat16 *qh, *ql, *kh, *kl, *vh, *vl, *ph, *pl, *ah, *al;
    cudaGetSymbolAddress((void**)&qkv, g_qkv);
    cudaGetSymbolAddress((void**)&S,   g_S);
    cudaGetSymbolAddress((void**)&att, g_att);
    cudaGetSymbolAddress((void**)&xh,  g_x_hi);   cudaGetSymbolAddress((void**)&xl,  g_x_lo);
    cudaGetSymbolAddress((void**)&wqh, g_wqkv_hi);cudaGetSymbolAddress((void**)&wql, g_wqkv_lo);
    cudaGetSymbolAddress((void**)&woh, g_wout_hi);cudaGetSymbolAddress((void**)&wol, g_wout_lo);
    cudaGetSymbolAddress((void**)&qh,  g_q_hi);   cudaGetSymbolAddress((void**)&ql,  g_q_lo);
    cudaGetSymbolAddress((void**)&kh,  g_k_hi);   cudaGetSymbolAddress((void**)&kl,  g_k_lo);
    cudaGetSymbolAddress((void**)&vh,  g_vt_hi);  cudaGetSymbolAddress((void**)&vl,  g_vt_lo);
    cudaGetSymbolAddress((void**)&ph,  g_p_hi);   cudaGetSymbolAddress((void**)&pl,  g_p_lo);
    cudaGetSymbolAddress((void**)&ah,  g_att_hi); cudaGetSymbolAddress((void**)&al,  g_att_lo);

    cudaFuncSetAttribute(gemm_bf16x3<0>, cudaFuncAttributeMaxDynamicSharedMemorySize, DYN_SMEM);
    cudaFuncSetAttribute(gemm_bf16x3<1>, cudaFuncAttributeMaxDynamicSharedMemorySize, DYN_SMEM);
    cudaFuncSetAttribute(gemm_bf16x3<2>, cudaFuncAttributeMaxDynamicSharedMemorySize, DYN_SMEM);

    const int   Bt = 4, Nseq = 2048, Din = 1024, Dinner = 512, Dout = 1024;
    const int   Mtot = Bt * Nseq;
    const float scale = rsqrtf((float)Dinner);
    dim3 blk(NTHREADS);

    // 0) input splits
    split_f32<<<2048, blk>>>(x, xh, xl, (long long)Mtot * Din);
    split_f32<<<512,  blk>>>(w_qkv, wqh, wql, (long long)(3 * Dinner) * Din);
    split_f32<<<256,  blk>>>(w_out, woh, wol, (long long)Dout * Dinner);

    // 1) QKV projection
    gemm_bf16x3<0><<<dim3((3 * Dinner) / 128, Mtot / 128, 1), blk, DYN_SMEM>>>(
        xh, xl, wqh, wql, qkv, nullptr,
        Din, Din, Din, 3 * Dinner, 0, 0, 0, 1.0f);

    // 2) extract q,k and transposed v (bf16 hi/lo)
    split_qk<<<2048, blk>>>(qkv, qh, ql, kh, kl);
    split_v_t<<<dim3(Nseq / 32, Dinner / 32, Bt), dim3(32, 8)>>>(qkv, vh, vl);

    // 3) S = scale * q.k^T (causal tile-skip)
    gemm_bf16x3<1><<<dim3(Nseq / 128, Nseq / 128, Bt), blk, DYN_SMEM>>>(
        qh, ql, kh, kl, S, nullptr,
        Dinner, Dinner, Dinner, Nseq,
        (long long)Nseq * Dinner, (long long)Nseq * Dinner,
        (long long)Nseq * Nseq, scale);

    // 4) causal softmax (zero-pads each row to its 128-tile boundary)
    softmax_causal<<<dim3(Nseq, Bt), blk>>>(S, Nseq);

    // 5) P -> bf16 hi/lo (padded region only)
    split_p<<<dim3(Nseq, Bt), blk>>>(S, ph, pl);

    // 6) att = P.V (K clamped per row tile)
    gemm_bf16x3<2><<<dim3(Dinner / 128, Nseq / 128, Bt), blk, DYN_SMEM>>>(
        ph, pl, vh, vl, att, nullptr,
        Nseq, Nseq, Nseq, Dinner,
        (long long)Nseq * Nseq, (long long)Dinner * Nseq,
        (long long)Nseq * Dinner, 1.0f);

    // 7) att -> bf16 hi/lo
    split_f32<<<2048, blk>>>(att, ah, al, (long long)Mtot * Dinner);

    // 8) out = att.w_out^T + b_out
    gemm_bf16x3<0><<<dim3(Dout / 128, Mtot / 128, 1), blk, DYN_SMEM>>>(
        ah, al, woh, wol, out, b_out,
        Dinner, Dinner, Dinner, Dout, 0, 0, 0, 1.0f);
}